// round 3
// baseline (speedup 1.0000x reference)
#include <cuda_runtime.h>

#define BATCH 8192
#define IN_F  1024
#define OUT_F 1024
#define NB    8      // basis functions per input (GRID + K)
#define NK    12     // extended knot count (GRID + 2K + 1)

#define BM  128      // batch tile
#define BN  128      // out tile
#define BKI 4        // input features per stage
#define KD  (BKI * 9)  // expanded K-depth per stage = 36

__device__ __forceinline__ void fma2(unsigned long long &d,
                                     unsigned long long a,
                                     unsigned long long b) {
    asm volatile("fma.rn.f32x2 %0, %1, %2, %0;" : "+l"(d) : "l"(a), "l"(b));
}

__device__ __forceinline__ unsigned long long pack2(float lo, float hi) {
    unsigned long long r;
    asm("mov.b64 %0, {%1, %2};" : "=l"(r) : "f"(lo), "f"(hi));
    return r;
}

__global__ __launch_bounds__(256)
void kan_fused_kernel(const float* __restrict__ x,     // (BATCH, IN_F)
                      const float* __restrict__ bw,    // (OUT_F, IN_F)
                      const float* __restrict__ sw,    // (OUT_F, IN_F, 8)
                      const float* __restrict__ grid,  // (IN_F, 12) rows identical
                      float* __restrict__ out)         // (BATCH, OUT_F)
{
    __shared__ float Fs[KD][BM];   // expanded features: row i*9+0 = x, +1..8 = basis
    __shared__ float Ws[KD][BN];   // expanded weights:  row i*9+0 = base, +1..8 = spline
    __shared__ float s_kn[NK];
    __shared__ float s_rL[30];
    __shared__ float s_rR[30];

    const int tid = threadIdx.x;
    const int bm0 = blockIdx.y * BM;
    const int on0 = blockIdx.x * BN;

    // --- knot vector + reciprocal denominator tables (uniform across i, use row 0)
    if (tid < NK) s_kn[tid] = grid[tid];
    __syncthreads();
    if (tid < 30) {
        int p = tid / 10 + 1;   // degree 1..3
        int j = tid % 10;
        if (j <= 10 - p) {
            s_rL[tid] = 1.0f / (s_kn[j + p]     - s_kn[j]);
            s_rR[tid] = 1.0f / (s_kn[j + p + 1] - s_kn[j + 1]);
        } else {
            s_rL[tid] = 0.0f;
            s_rR[tid] = 0.0f;
        }
    }

    const int ty = tid >> 4;     // 0..15 -> M micro-tile
    const int tx = tid & 15;     // 0..15 -> N micro-tile

    unsigned long long acc[8][4];
#pragma unroll
    for (int m = 0; m < 8; m++)
#pragma unroll
        for (int n = 0; n < 4; n++) acc[m][n] = 0ull;

    const int  o_local = tid & 127;
    const int  part    = tid >> 7;            // 0 or 1
    const long o       = (long)on0 + o_local;

    for (int i0 = 0; i0 < IN_F; i0 += BKI) {
        __syncthreads();

        // ---------------- load expanded weight tile ----------------
        if (part == 0) {
#pragma unroll
            for (int ii = 0; ii < 2; ii++) {
                const float4* sp = (const float4*)(sw + ((o * IN_F + (i0 + ii)) << 3));
                float4 s0 = sp[0];
                float4 s1 = sp[1];
                Ws[ii*9 + 1][o_local] = s0.x;  Ws[ii*9 + 2][o_local] = s0.y;
                Ws[ii*9 + 3][o_local] = s0.z;  Ws[ii*9 + 4][o_local] = s0.w;
                Ws[ii*9 + 5][o_local] = s1.x;  Ws[ii*9 + 6][o_local] = s1.y;
                Ws[ii*9 + 7][o_local] = s1.z;  Ws[ii*9 + 8][o_local] = s1.w;
            }
        } else {
#pragma unroll
            for (int ii = 2; ii < 4; ii++) {
                const float4* sp = (const float4*)(sw + ((o * IN_F + (i0 + ii)) << 3));
                float4 s0 = sp[0];
                float4 s1 = sp[1];
                Ws[ii*9 + 1][o_local] = s0.x;  Ws[ii*9 + 2][o_local] = s0.y;
                Ws[ii*9 + 3][o_local] = s0.z;  Ws[ii*9 + 4][o_local] = s0.w;
                Ws[ii*9 + 5][o_local] = s1.x;  Ws[ii*9 + 6][o_local] = s1.y;
                Ws[ii*9 + 7][o_local] = s1.z;  Ws[ii*9 + 8][o_local] = s1.w;
            }
            float4 bv = *(const float4*)(bw + o * IN_F + i0);
            Ws[ 0][o_local] = bv.x;
            Ws[ 9][o_local] = bv.y;
            Ws[18][o_local] = bv.z;
            Ws[27][o_local] = bv.w;
        }

        // ---------------- load x tile + expand B-spline basis ----------------
#pragma unroll
        for (int r = 0; r < 2; r++) {
            int idx = tid + r * 256;        // 0..511
            int bl  = idx & 127;            // batch within tile
            int il  = idx >> 7;             // input feature within chunk (0..3)
            float xv = x[(long)(bm0 + bl) * IN_F + (i0 + il)];

            float b[11];
#pragma unroll
            for (int j = 0; j < 11; j++)
                b[j] = (xv >= s_kn[j] && xv < s_kn[j + 1]) ? 1.0f : 0.0f;
#pragma unroll
            for (int p = 1; p <= 3; p++) {
#pragma unroll
                for (int j = 0; j <= 10 - p; j++) {
                    b[j] = (xv - s_kn[j])         * s_rL[(p - 1) * 10 + j] * b[j]
                         + (s_kn[j + p + 1] - xv) * s_rR[(p - 1) * 10 + j] * b[j + 1];
                }
            }
            Fs[il * 9 + 0][bl] = xv;
#pragma unroll
            for (int c = 0; c < NB; c++)
                Fs[il * 9 + 1 + c][bl] = b[c];
        }

        __syncthreads();

        // ---------------- 128x128x36 FMA stage (f32x2 packed) ----------------
#pragma unroll
        for (int k = 0; k < KD; k++) {
            float4 a0 = *(const float4*)&Fs[k][ty * 8];
            float4 a1 = *(const float4*)&Fs[k][ty * 8 + 4];
            float4 b0 = *(const float4*)&Ws[k][tx * 8];
            float4 b1 = *(const float4*)&Ws[k][tx * 8 + 4];

            unsigned long long bb[4];
            bb[0] = pack2(b0.x, b0.y);
            bb[1] = pack2(b0.z, b0.w);
            bb[2] = pack2(b1.x, b1.y);
            bb[3] = pack2(b1.z, b1.w);

            float av[8] = {a0.x, a0.y, a0.z, a0.w, a1.x, a1.y, a1.z, a1.w};
#pragma unroll
            for (int m = 0; m < 8; m++) {
                unsigned long long aa = pack2(av[m], av[m]);
#pragma unroll
                for (int n = 0; n < 4; n++)
                    fma2(acc[m][n], aa, bb[n]);
            }
        }
    }

    // ---------------- epilogue ----------------
#pragma unroll
    for (int m = 0; m < 8; m++) {
        long row = (long)bm0 + ty * 8 + m;
        float* op = out + row * OUT_F + on0 + tx * 8;
#pragma unroll
        for (int n = 0; n < 4; n++) {
            float2 v = *(float2*)&acc[m][n];
            *(float2*)(op + 2 * n) = v;
        }
    }
}

extern "C" void kernel_launch(void* const* d_in, const int* in_sizes, int n_in,
                              void* d_out, int out_size) {
    const float* x  = (const float*)d_in[0];   // (8192, 1024)
    const float* bw = (const float*)d_in[1];   // (1024, 1024)
    const float* sw = (const float*)d_in[2];   // (1024, 1024, 8)
    const float* gr = (const float*)d_in[3];   // (1024, 12)
    float* out = (float*)d_out;                // (8192, 1024)

    dim3 grid(OUT_F / BN, BATCH / BM);         // (8, 64)
    dim3 block(256);
    kan_fused_kernel<<<grid, block>>>(x, bw, sw, gr, out);
}

// round 5
// speedup vs baseline: 1.7697x; 1.7697x over previous
#include <cuda_runtime.h>
#include <cuda_bf16.h>
#include <cstdint>

#define BM 128
#define BN 128
#define NST 128            // stages; 8 input features per stage
#define SLOTS 80           // K-slots per stage (8 features x 10)
#define KS 88              // padded SMEM row stride in bf16 elements
#define ROWB (KS*2)        // 176 bytes per row
#define PLB (128*ROWB)     // plane bytes = 22528
#define BUFB (4*PLB)       // Ah, Al, Bh, Bl = 90112
#define SMEM_TOT (2*BUFB)  // 180224

// pre-expanded weights, stage-major: [stage][n][80] bf16, hi and lo planes
__device__ __align__(16) __nv_bfloat16 g_wh[(size_t)NST * 1024 * SLOTS];
__device__ __align__(16) __nv_bfloat16 g_wl[(size_t)NST * 1024 * SLOTS];

static __device__ __forceinline__ uint32_t s2u(const void* p) {
    uint32_t a;
    asm("{ .reg .u64 t; cvta.to.shared.u64 t, %1; cvt.u32.u64 %0, t; }" : "=r"(a) : "l"(p));
    return a;
}

static __device__ __forceinline__ void cp16(uint32_t dst, const void* src) {
    asm volatile("cp.async.cg.shared.global [%0], [%1], 16;" :: "r"(dst), "l"(src));
}

static __device__ __forceinline__ uint32_t packbf(float a, float b) {
    __nv_bfloat16 ha = __float2bfloat16(a), hb = __float2bfloat16(b);
    uint16_t ua, ub;
    memcpy(&ua, &ha, 2); memcpy(&ub, &hb, 2);
    return (uint32_t)ua | ((uint32_t)ub << 16);
}

static __device__ __forceinline__ void mma16816(float* c, uint32_t a0, uint32_t a1,
                                                uint32_t a2, uint32_t a3,
                                                uint32_t b0, uint32_t b1) {
    asm volatile("mma.sync.aligned.m16n8k16.row.col.f32.bf16.bf16.f32 "
                 "{%0,%1,%2,%3}, {%4,%5,%6,%7}, {%8,%9}, {%0,%1,%2,%3};"
                 : "+f"(c[0]), "+f"(c[1]), "+f"(c[2]), "+f"(c[3])
                 : "r"(a0), "r"(a1), "r"(a2), "r"(a3), "r"(b0), "r"(b1));
}

// ---------------- prep: expand + hi/lo split weights into stage-major layout ----------------
__global__ void wexp_kernel(const float* __restrict__ bw, const float* __restrict__ sw) {
    int n = blockIdx.x;      // 0..1023 (output feature)
    int s = threadIdx.x;     // 0..127  (stage)
    __nv_bfloat16 hi[SLOTS], lo[SLOTS];
    const float* bwr = bw + (size_t)n * 1024 + s * 8;
    const float* swr = sw + ((size_t)n * 1024 + (size_t)s * 8) * 8;
#pragma unroll
    for (int f = 0; f < 8; f++) {
        float v[10];
        v[0] = bwr[f];
#pragma unroll
        for (int j = 0; j < 8; j++) v[1 + j] = swr[f * 8 + j];
        v[9] = 0.f;
#pragma unroll
        for (int j = 0; j < 10; j++) {
            __nv_bfloat16 h = __float2bfloat16(v[j]);
            hi[f * 10 + j] = h;
            lo[f * 10 + j] = __float2bfloat16(v[j] - __bfloat162float(h));
        }
    }
    uint4* dh = (uint4*)(g_wh + ((size_t)s * 1024 + n) * SLOTS);
    uint4* dl = (uint4*)(g_wl + ((size_t)s * 1024 + n) * SLOTS);
#pragma unroll
    for (int j = 0; j < 10; j++) { dh[j] = ((uint4*)hi)[j]; dl[j] = ((uint4*)lo)[j]; }
}

// ---------------- main fused GEMM ----------------
__global__ __launch_bounds__(256, 1)
void kan_mma(const float* __restrict__ x, const float* __restrict__ gr,
             float* __restrict__ out) {
    extern __shared__ char smem[];
    __shared__ float s_kn[12], s_rL[30], s_rR[30];

    const int tid  = threadIdx.x;
    const int lane = tid & 31, wid = tid >> 5;
    const int on0  = blockIdx.x * BN, bm0 = blockIdx.y * BM;

    if (tid < 12) s_kn[tid] = gr[tid];
    __syncthreads();
    if (tid < 30) {
        int p = tid / 10 + 1, j = tid % 10;
        if (j <= 10 - p) {
            s_rL[tid] = 1.f / (s_kn[j + p] - s_kn[j]);
            s_rR[tid] = 1.f / (s_kn[j + p + 1] - s_kn[j + 1]);
        } else { s_rL[tid] = 0.f; s_rR[tid] = 0.f; }
    }
    __syncthreads();

    const uint32_t sb = s2u(smem);

    // producer roles
    const int prow = tid >> 1, pq = tid & 1;     // A: row 0..127, feature-quad 0/1
    const int brow = tid & 127, bpl = tid >> 7;  // B: n-row, plane (0=hi,1=lo)
    const __nv_bfloat16* bsrc_base = (bpl ? g_wl : g_wh) + ((size_t)on0 + brow) * SLOTS;

    // compute roles: 8 warps = 2 (M) x 4 (N); warp tile 64x32
    const int wm = wid >> 2, wn = wid & 3;
    const int g = lane >> 2, t = lane & 3;

    float acc[4][4][4];
#pragma unroll
    for (int mt = 0; mt < 4; mt++)
#pragma unroll
        for (int nt = 0; nt < 4; nt++)
#pragma unroll
            for (int r = 0; r < 4; r++) acc[mt][nt][r] = 0.f;

    float4 xv;

    // ---- producer helpers (inlined via lambdas) ----
    auto issueB = [&](int s, int buf) {
        const __nv_bfloat16* src = bsrc_base + (size_t)s * 1024 * SLOTS;
        uint32_t dst = sb + buf * BUFB + (2 + bpl) * PLB + brow * ROWB;
#pragma unroll
        for (int j = 0; j < 10; j++) cp16(dst + j * 16, src + j * 8);
        asm volatile("cp.async.commit_group;" ::: "memory");
    };
    auto loadX = [&](int s) {
        xv = *(const float4*)(x + (size_t)(bm0 + prow) * 1024 + s * 8 + pq * 4);
    };
    auto expandA = [&](int buf) {
        char* base = smem + buf * BUFB + prow * ROWB;
#pragma unroll
        for (int ff = 0; ff < 4; ff++) {
            int f = pq * 4 + ff;
            float v0 = (&xv.x)[ff];
            float b[11];
#pragma unroll
            for (int j = 0; j < 11; j++) b[j] = (v0 >= s_kn[j] && v0 < s_kn[j + 1]) ? 1.f : 0.f;
#pragma unroll
            for (int p = 1; p <= 3; p++)
#pragma unroll
                for (int j = 0; j <= 10 - p; j++)
                    b[j] = (v0 - s_kn[j]) * s_rL[(p - 1) * 10 + j] * b[j]
                         + (s_kn[j + p + 1] - v0) * s_rR[(p - 1) * 10 + j] * b[j + 1];
            float v[10];
            v[0] = v0;
#pragma unroll
            for (int c = 0; c < 8; c++) v[1 + c] = b[c];
            v[9] = 0.f;
            uint32_t* dh = (uint32_t*)(base + f * 20);
            uint32_t* dl = (uint32_t*)(base + PLB + f * 20);
#pragma unroll
            for (int j = 0; j < 5; j++) {
                float e0 = v[2 * j], e1 = v[2 * j + 1];
                __nv_bfloat16 h0 = __float2bfloat16(e0), h1 = __float2bfloat16(e1);
                dh[j] = packbf(e0, e1);
                dl[j] = packbf(e0 - __bfloat162float(h0), e1 - __bfloat162float(h1));
            }
        }
    };

    // ---- prologue: fill buffer 0 with stage 0 ----
    issueB(0, 0);
    loadX(0);
    expandA(0);
    asm volatile("cp.async.wait_group 0;" ::: "memory");
    __syncthreads();

    for (int s = 0; s < NST; ++s) {
        const int buf = s & 1, nbuf = buf ^ 1;
        if (s + 1 < NST) { issueB(s + 1, nbuf); loadX(s + 1); }

        // ---- compute: 5 k16 steps over buf ----
        const char* Bu = smem + buf * BUFB;
#pragma unroll
        for (int kk = 0; kk < 5; kk++) {
            const int kb = kk * 16;
            uint32_t Bh[4][2], Bl[4][2];
#pragma unroll
            for (int nt = 0; nt < 4; nt++) {
                int n = wn * 32 + nt * 8 + g;
                const uint32_t* ph = (const uint32_t*)(Bu + 2 * PLB + n * ROWB + (kb + 2 * t) * 2);
                Bh[nt][0] = ph[0]; Bh[nt][1] = ph[4];
                const uint32_t* pl = (const uint32_t*)(Bu + 3 * PLB + n * ROWB + (kb + 2 * t) * 2);
                Bl[nt][0] = pl[0]; Bl[nt][1] = pl[4];
            }
#pragma unroll
            for (int mt = 0; mt < 4; mt++) {
                int r = wm * 64 + mt * 16 + g;
                const char* pa = Bu + r * ROWB + (kb + 2 * t) * 2;
                uint32_t ah0 = *(const uint32_t*)(pa);
                uint32_t ah1 = *(const uint32_t*)(pa + 8 * ROWB);
                uint32_t ah2 = *(const uint32_t*)(pa + 16);
                uint32_t ah3 = *(const uint32_t*)(pa + 8 * ROWB + 16);
                uint32_t al0 = *(const uint32_t*)(pa + PLB);
                uint32_t al1 = *(const uint32_t*)(pa + PLB + 8 * ROWB);
                uint32_t al2 = *(const uint32_t*)(pa + PLB + 16);
                uint32_t al3 = *(const uint32_t*)(pa + PLB + 8 * ROWB + 16);
#pragma unroll
                for (int nt = 0; nt < 4; nt++) {
                    mma16816(acc[mt][nt], ah0, ah1, ah2, ah3, Bh[nt][0], Bh[nt][1]);
                    mma16816(acc[mt][nt], ah0, ah1, ah2, ah3, Bl[nt][0], Bl[nt][1]);
                    mma16816(acc[mt][nt], al0, al1, al2, al3, Bh[nt][0], Bh[nt][1]);
                }
            }
        }

        if (s + 1 < NST) {
            expandA(nbuf);
            asm volatile("cp.async.wait_group 0;" ::: "memory");
        }
        __syncthreads();
    }

    // ---- epilogue ----
#pragma unroll
    for (int mt = 0; mt < 4; mt++) {
#pragma unroll
        for (int nt = 0; nt < 4; nt++) {
            int r = bm0 + wm * 64 + mt * 16 + g;
            int c = on0 + wn * 32 + nt * 8 + 2 * t;
            *(float2*)(out + (size_t)r * 1024 + c)       = make_float2(acc[mt][nt][0], acc[mt][nt][1]);
            *(float2*)(out + (size_t)(r + 8) * 1024 + c) = make_float2(acc[mt][nt][2], acc[mt][nt][3]);
        }
    }
}

extern "C" void kernel_launch(void* const* d_in, const int* in_sizes, int n_in,
                              void* d_out, int out_size) {
    const float* x  = (const float*)d_in[0];   // (8192, 1024)
    const float* bw = (const float*)d_in[1];   // (1024, 1024)
    const float* sw = (const float*)d_in[2];   // (1024, 1024, 8)
    const float* gr = (const float*)d_in[3];   // (1024, 12)
    float* out = (float*)d_out;                // (8192, 1024)

    cudaFuncSetAttribute(kan_mma, cudaFuncAttributeMaxDynamicSharedMemorySize, SMEM_TOT);
    wexp_kernel<<<1024, 128>>>(bw, sw);
    kan_mma<<<dim3(8, 64), 256, SMEM_TOT>>>(x, gr, out);
}

// round 6
// speedup vs baseline: 2.1525x; 1.2163x over previous
#include <cuda_runtime.h>
#include <cuda_bf16.h>
#include <cstdint>

#define BM 128
#define BN 128
#define NST 128            // stages; 8 input features per stage
#define SLOTS 80           // K-slots per stage (8 features x 10)
#define KS 88              // padded SMEM row stride in bf16 elements
#define ROWB (KS*2)        // 176 bytes per row
#define PLB (128*ROWB)     // plane bytes = 22528
#define BUFB (4*PLB)       // Ah, Al, Bh, Bl = 90112
#define SMEM_TOT (2*BUFB)  // 180224
#define NTHR 384           // 8 compute warps + 4 producer warps

// pre-expanded weights, stage-major: [stage][n][80] bf16, hi and lo planes
__device__ __align__(16) __nv_bfloat16 g_wh[(size_t)NST * 1024 * SLOTS];
__device__ __align__(16) __nv_bfloat16 g_wl[(size_t)NST * 1024 * SLOTS];

static __device__ __forceinline__ uint32_t s2u(const void* p) {
    uint32_t a;
    asm("{ .reg .u64 t; cvta.to.shared.u64 t, %1; cvt.u32.u64 %0, t; }" : "=r"(a) : "l"(p));
    return a;
}
static __device__ __forceinline__ void cp16(uint32_t dst, const void* src) {
    asm volatile("cp.async.cg.shared.global [%0], [%1], 16;" :: "r"(dst), "l"(src));
}
static __device__ __forceinline__ uint32_t packbf(float a, float b) {
    __nv_bfloat16 ha = __float2bfloat16(a), hb = __float2bfloat16(b);
    uint16_t ua, ub;
    memcpy(&ua, &ha, 2); memcpy(&ub, &hb, 2);
    return (uint32_t)ua | ((uint32_t)ub << 16);
}
static __device__ __forceinline__ void ldm4(uint32_t* r, uint32_t addr) {
    asm volatile("ldmatrix.sync.aligned.m8n8.x4.shared.b16 {%0,%1,%2,%3}, [%4];"
                 : "=r"(r[0]), "=r"(r[1]), "=r"(r[2]), "=r"(r[3]) : "r"(addr));
}
static __device__ __forceinline__ void mma16816(float* c, const uint32_t* a,
                                                uint32_t b0, uint32_t b1) {
    asm volatile("mma.sync.aligned.m16n8k16.row.col.f32.bf16.bf16.f32 "
                 "{%0,%1,%2,%3}, {%4,%5,%6,%7}, {%8,%9}, {%0,%1,%2,%3};"
                 : "+f"(c[0]), "+f"(c[1]), "+f"(c[2]), "+f"(c[3])
                 : "r"(a[0]), "r"(a[1]), "r"(a[2]), "r"(a[3]), "r"(b0), "r"(b1));
}

// ---------------- prep: expand + hi/lo split weights into stage-major layout ----------------
__global__ void wexp_kernel(const float* __restrict__ bw, const float* __restrict__ sw) {
    int n = blockIdx.x;      // output feature
    int s = threadIdx.x;     // stage
    __nv_bfloat16 hi[SLOTS], lo[SLOTS];
    const float* bwr = bw + (size_t)n * 1024 + s * 8;
    const float* swr = sw + ((size_t)n * 1024 + (size_t)s * 8) * 8;
#pragma unroll
    for (int f = 0; f < 8; f++) {
        float v[10];
        v[0] = bwr[f];
#pragma unroll
        for (int j = 0; j < 8; j++) v[1 + j] = swr[f * 8 + j];
        v[9] = 0.f;
#pragma unroll
        for (int j = 0; j < 10; j++) {
            __nv_bfloat16 h = __float2bfloat16(v[j]);
            hi[f * 10 + j] = h;
            lo[f * 10 + j] = __float2bfloat16(v[j] - __bfloat162float(h));
        }
    }
    uint4* dh = (uint4*)(g_wh + ((size_t)s * 1024 + n) * SLOTS);
    uint4* dl = (uint4*)(g_wl + ((size_t)s * 1024 + n) * SLOTS);
#pragma unroll
    for (int j = 0; j < 10; j++) { dh[j] = ((uint4*)hi)[j]; dl[j] = ((uint4*)lo)[j]; }
}

// ---------------- main fused GEMM (warp-specialized) ----------------
__global__ __launch_bounds__(NTHR, 1)
void kan_mma(const float* __restrict__ x, const float* __restrict__ gr,
             float* __restrict__ out) {
    extern __shared__ char smem[];
    __shared__ float s_kn[12], s_rL[30], s_rR[30];

    const int tid  = threadIdx.x;
    const int lane = tid & 31, wid = tid >> 5;
    const int on0  = blockIdx.x * BN, bm0 = blockIdx.y * BM;
    const uint32_t sb = s2u(smem);

    if (tid < 12) s_kn[tid] = gr[tid];
    __syncthreads();
    if (tid < 30) {
        int p = tid / 10 + 1, j = tid % 10;
        if (j <= 10 - p) {
            s_rL[tid] = 1.f / (s_kn[j + p] - s_kn[j]);
            s_rR[tid] = 1.f / (s_kn[j + p + 1] - s_kn[j + 1]);
        } else { s_rL[tid] = 0.f; s_rR[tid] = 0.f; }
    }
    __syncthreads();

    if (wid >= 8) {
        // ======================= PRODUCER WARPS (128 threads) =======================
        const int row = tid - 256;                 // 0..127
        const __nv_bfloat16* bh_src = g_wh + ((size_t)on0 + row) * SLOTS;
        const __nv_bfloat16* bl_src = g_wl + ((size_t)on0 + row) * SLOTS;
        const float* xrow = x + (size_t)(bm0 + row) * 1024;

        auto fill = [&](int s, int buf) {
            const uint32_t bo = sb + buf * BUFB;
            // --- B hi/lo planes via cp.async ---
            const size_t soff = (size_t)s * 1024 * SLOTS;
            uint32_t dh = bo + 2 * PLB + row * ROWB;
            uint32_t dl = bo + 3 * PLB + row * ROWB;
#pragma unroll
            for (int j = 0; j < 10; j++) {
                cp16(dh + j * 16, bh_src + soff + j * 8);
                cp16(dl + j * 16, bl_src + soff + j * 8);
            }
            asm volatile("cp.async.commit_group;" ::: "memory");
            // --- A expand: 8 features for this batch row ---
            float4 x0 = *(const float4*)(xrow + s * 8);
            float4 x1 = *(const float4*)(xrow + s * 8 + 4);
            float xs[8] = {x0.x, x0.y, x0.z, x0.w, x1.x, x1.y, x1.z, x1.w};
            char* abase = smem + buf * BUFB + row * ROWB;
#pragma unroll
            for (int f = 0; f < 8; f++) {
                float v0 = xs[f];
                float b[11];
#pragma unroll
                for (int j = 0; j < 11; j++) b[j] = (v0 >= s_kn[j] && v0 < s_kn[j + 1]) ? 1.f : 0.f;
#pragma unroll
                for (int p = 1; p <= 3; p++)
#pragma unroll
                    for (int j = 0; j <= 10 - p; j++)
                        b[j] = (v0 - s_kn[j]) * s_rL[(p - 1) * 10 + j] * b[j]
                             + (s_kn[j + p + 1] - v0) * s_rR[(p - 1) * 10 + j] * b[j + 1];
                float v[10];
                v[0] = v0;
#pragma unroll
                for (int c = 0; c < 8; c++) v[1 + c] = b[c];
                v[9] = 0.f;
                uint32_t* wh = (uint32_t*)(abase + f * 20);
                uint32_t* wl = (uint32_t*)(abase + PLB + f * 20);
#pragma unroll
                for (int j = 0; j < 5; j++) {
                    float e0 = v[2 * j], e1 = v[2 * j + 1];
                    __nv_bfloat16 h0 = __float2bfloat16(e0), h1 = __float2bfloat16(e1);
                    wh[j] = packbf(e0, e1);
                    wl[j] = packbf(e0 - __bfloat162float(h0), e1 - __bfloat162float(h1));
                }
            }
            asm volatile("cp.async.wait_group 0;" ::: "memory");
        };

        fill(0, 0);
        __syncthreads();                       // buf0 ready
        for (int s = 0; s < NST; ++s) {
            if (s + 1 < NST) fill(s + 1, (s + 1) & 1);
            __syncthreads();                   // stage s consumed / s+1 ready
        }
    } else {
        // ======================= COMPUTE WARPS (256 threads) =======================
        const int wm = wid >> 2, wn = wid & 3;     // 2 x 4 warps, 64x32 tile each
        const int g = lane >> 2, t = lane & 3;

        // ldmatrix per-lane offsets
        const uint32_t a_off = (uint32_t)((((lane >> 3) & 1) * 8 + (lane & 7)) * ROWB
                                          + (lane >> 4) * 16);
        const uint32_t b_off = (uint32_t)((((lane >> 4) * 8) + (lane & 7)) * ROWB
                                          + ((lane >> 3) & 1) * 16);

        float acc[4][4][4];
#pragma unroll
        for (int mt = 0; mt < 4; mt++)
#pragma unroll
            for (int nt = 0; nt < 4; nt++)
#pragma unroll
                for (int r = 0; r < 4; r++) acc[mt][nt][r] = 0.f;

        __syncthreads();                       // wait buf0
        for (int s = 0; s < NST; ++s) {
            const uint32_t bo = sb + (s & 1) * BUFB;
            const uint32_t Ah = bo + wm * 64 * ROWB + a_off;
            const uint32_t Al = Ah + PLB;
            const uint32_t Bh = bo + 2 * PLB + wn * 32 * ROWB + b_off;
            const uint32_t Bl = Bh + PLB;
#pragma unroll
            for (int kk = 0; kk < 5; kk++) {
                const uint32_t kb = kk * 32;
                uint32_t bh[8], bl[8];                     // [pair*4 + reg]
                ldm4(bh,     Bh + kb);                     // nt0, nt1
                ldm4(bh + 4, Bh + 16 * ROWB + kb);         // nt2, nt3
                ldm4(bl,     Bl + kb);
                ldm4(bl + 4, Bl + 16 * ROWB + kb);
#pragma unroll
                for (int mt = 0; mt < 4; mt++) {
                    uint32_t ah[4], al[4];
                    ldm4(ah, Ah + mt * 16 * ROWB + kb);
                    ldm4(al, Al + mt * 16 * ROWB + kb);
#pragma unroll
                    for (int nt = 0; nt < 4; nt++) {
                        uint32_t B0 = (nt & 1) ? ((nt >> 1) ? bh[6] : bh[2]) : ((nt >> 1) ? bh[4] : bh[0]);
                        uint32_t B1 = (nt & 1) ? ((nt >> 1) ? bh[7] : bh[3]) : ((nt >> 1) ? bh[5] : bh[1]);
                        uint32_t C0 = (nt & 1) ? ((nt >> 1) ? bl[6] : bl[2]) : ((nt >> 1) ? bl[4] : bl[0]);
                        uint32_t C1 = (nt & 1) ? ((nt >> 1) ? bl[7] : bl[3]) : ((nt >> 1) ? bl[5] : bl[1]);
                        mma16816(acc[mt][nt], ah, B0, B1);
                        mma16816(acc[mt][nt], ah, C0, C1);
                        mma16816(acc[mt][nt], al, B0, B1);
                    }
                }
            }
            __syncthreads();
        }

        // ---- epilogue ----
#pragma unroll
        for (int mt = 0; mt < 4; mt++) {
#pragma unroll
            for (int nt = 0; nt < 4; nt++) {
                int r = bm0 + wm * 64 + mt * 16 + g;
                int c = on0 + wn * 32 + nt * 8 + 2 * t;
                *(float2*)(out + (size_t)r * 1024 + c)       = make_float2(acc[mt][nt][0], acc[mt][nt][1]);
                *(float2*)(out + (size_t)(r + 8) * 1024 + c) = make_float2(acc[mt][nt][2], acc[mt][nt][3]);
            }
        }
    }
}

extern "C" void kernel_launch(void* const* d_in, const int* in_sizes, int n_in,
                              void* d_out, int out_size) {
    const float* x  = (const float*)d_in[0];   // (8192, 1024)
    const float* bw = (const float*)d_in[1];   // (1024, 1024)
    const float* sw = (const float*)d_in[2];   // (1024, 1024, 8)
    const float* gr = (const float*)d_in[3];   // (1024, 12)
    float* out = (float*)d_out;                // (8192, 1024)

    cudaFuncSetAttribute(kan_mma, cudaFuncAttributeMaxDynamicSharedMemorySize, SMEM_TOT);
    wexp_kernel<<<1024, 128>>>(bw, sw);
    kan_mma<<<dim3(8, 64), NTHR, SMEM_TOT>>>(x, gr, out);
}